// round 1
// baseline (speedup 1.0000x reference)
#include <cuda_runtime.h>
#include <cstdint>
#include <math.h>

#define NPIX 131072          // 4*128*256
#define DIM 720
#define NCLS 19
#define NPROTO 10
#define NJ 190               // NCLS*NPROTO
#define HW 32768             // 128*256

// ---------------- scratch (device globals; no runtime allocation) ----------------
__device__ float g_c[(size_t)NPIX * DIM];     // normalized features (377MB)
__device__ float g_protos[NJ * DIM];          // l2-normalized prototypes
__device__ float g_r[3 * NJ];                 // sinkhorn row sums (3 rounds)
__device__ float g_a[NJ];                     // sinkhorn row factors
__device__ int   g_clscnt[NCLS];              // |S_k| per class
__device__ unsigned char g_corr[NPIX];        // pred==gt flag
__device__ float g_f[NJ * DIM];               // prototype accumulators
__device__ float g_cntkm[NJ];                 // per-(k,m) counts

// ---------------- zero scratch ----------------
__global__ void zero_kernel() {
    int i = blockIdx.x * blockDim.x + threadIdx.x;
    if (i < NJ * DIM) g_f[i] = 0.f;
    if (i < 3 * NJ) g_r[i] = 0.f;
    if (i < NJ) g_cntkm[i] = 0.f;
    if (i < NCLS) g_clscnt[i] = 0;
}

// ---------------- K1: normalize prototypes ----------------
__global__ void proto_norm_kernel(const float* __restrict__ P) {
    __shared__ float red[256];
    int j = blockIdx.x;
    int tid = threadIdx.x;
    const float* row = P + j * DIM;
    float ss = 0.f;
    for (int d = tid; d < DIM; d += 256) { float v = row[d]; ss += v * v; }
    red[tid] = ss; __syncthreads();
    for (int s = 128; s > 0; s >>= 1) { if (tid < s) red[tid] += red[tid + s]; __syncthreads(); }
    float inv = 1.f / fmaxf(sqrtf(red[0]), 1e-12f);
    for (int d = tid; d < DIM; d += 256) g_protos[j * DIM + d] = row[d] * inv;
}

// ---------------- K2: per-pixel layernorm + L2 normalize ----------------
__global__ __launch_bounds__(256) void feat_kernel(const float* __restrict__ c,
                                                   const float* __restrict__ fg,
                                                   const float* __restrict__ fb) {
    __shared__ float sg[DIM], sb[DIM];
    for (int d = threadIdx.x; d < DIM; d += 256) { sg[d] = fg[d]; sb[d] = fb[d]; }
    __syncthreads();
    int n = blockIdx.x * 256 + threadIdx.x;
    const size_t base = (size_t)(n >> 15) * ((size_t)DIM * HW) + (size_t)(n & (HW - 1));
    float sx = 0.f, sxx = 0.f, s1 = 0.f, s2 = 0.f, s3 = 0.f, sg2 = 0.f, sgb = 0.f, sbb = 0.f;
#pragma unroll 4
    for (int d = 0; d < DIM; d++) {
        float x = c[base + (size_t)d * HW];
        float gd = sg[d], bd = sb[d];
        sx += x; sxx += x * x;
        float gx = gd * x;
        s1 += gx * gx; s2 += gd * gx; s3 += bd * gx;
        sg2 += gd * gd; sgb += gd * bd; sbb += bd * bd;
    }
    float mu = sx * (1.f / DIM);
    float var = sxx * (1.f / DIM) - mu * mu;
    float rs = rsqrtf(var + 1e-5f);
    float ss = rs * rs * (s1 - 2.f * mu * s2 + mu * mu * sg2) + 2.f * rs * (s3 - mu * sgb) + sbb;
    float linv = 1.f / fmaxf(sqrtf(ss), 1e-12f);
    float* out = g_c + (size_t)n * DIM;
#pragma unroll 4
    for (int d = 0; d < DIM; d++) {
        float x = c[base + (size_t)d * HW];
        out[d] = ((x - mu) * rs * sg[d] + sb[d]) * linv;
    }
}

// ---------------- K3: GEMM logits = _c @ protos^T, 3xTF32 mma ----------------
#define KC 24
#define KPAD 28

__device__ __forceinline__ void cvt_split(float x, float& hi, float& lo) {
    unsigned u;
    asm("cvt.rna.tf32.f32 %0, %1;" : "=r"(u) : "f"(x));
    hi = __uint_as_float(u);
    float r = x - hi;
    asm("cvt.rna.tf32.f32 %0, %1;" : "=r"(u) : "f"(r));
    lo = __uint_as_float(u);
}

#define MMA8(C, A0, A1, A2, A3, B0, B1)                                               \
    asm volatile("mma.sync.aligned.m16n8k8.row.col.f32.tf32.tf32.f32 "                 \
                 "{%0,%1,%2,%3},{%4,%5,%6,%7},{%8,%9},{%0,%1,%2,%3};"                  \
                 : "+f"(C[0]), "+f"(C[1]), "+f"(C[2]), "+f"(C[3])                      \
                 : "r"(__float_as_uint(A0)), "r"(__float_as_uint(A1)),                 \
                   "r"(__float_as_uint(A2)), "r"(__float_as_uint(A3)),                 \
                   "r"(__float_as_uint(B0)), "r"(__float_as_uint(B1)))

__global__ __launch_bounds__(256) void gemm_kernel(float* __restrict__ L) {
    __shared__ float AsH[128][KPAD], AsL[128][KPAD];
    __shared__ float BsH[64][KPAD], BsL[64][KPAD];
    int tid = threadIdx.x;
    int warp = tid >> 5, lane = tid & 31;
    int n0 = blockIdx.y * 128;
    int j0 = blockIdx.x * 64;
    float acc[8][4];
#pragma unroll
    for (int i = 0; i < 8; i++)
#pragma unroll
        for (int q = 0; q < 4; q++) acc[i][q] = 0.f;

    for (int kk = 0; kk < DIM; kk += KC) {
        // load A tile: 128 rows x 24 cols = 768 float4-loads of 6 per row
#pragma unroll
        for (int it = 0; it < 3; it++) {
            int idx = tid + it * 256;
            int r = idx / 6, c4 = idx % 6;
            const float4 v = *reinterpret_cast<const float4*>(
                &g_c[(size_t)(n0 + r) * DIM + kk + c4 * 4]);
            float h, l;
            cvt_split(v.x, h, l); AsH[r][c4 * 4 + 0] = h; AsL[r][c4 * 4 + 0] = l;
            cvt_split(v.y, h, l); AsH[r][c4 * 4 + 1] = h; AsL[r][c4 * 4 + 1] = l;
            cvt_split(v.z, h, l); AsH[r][c4 * 4 + 2] = h; AsL[r][c4 * 4 + 2] = l;
            cvt_split(v.w, h, l); AsH[r][c4 * 4 + 3] = h; AsL[r][c4 * 4 + 3] = l;
        }
        // load B tile: 64 rows x 24 cols (guard j<190)
#pragma unroll
        for (int it = 0; it < 2; it++) {
            int idx = tid + it * 256;
            if (idx < 384) {
                int r = idx / 6, c4 = idx % 6;
                int j = j0 + r;
                float4 v = make_float4(0.f, 0.f, 0.f, 0.f);
                if (j < NJ)
                    v = *reinterpret_cast<const float4*>(&g_protos[j * DIM + kk + c4 * 4]);
                float h, l;
                cvt_split(v.x, h, l); BsH[r][c4 * 4 + 0] = h; BsL[r][c4 * 4 + 0] = l;
                cvt_split(v.y, h, l); BsH[r][c4 * 4 + 1] = h; BsL[r][c4 * 4 + 1] = l;
                cvt_split(v.z, h, l); BsH[r][c4 * 4 + 2] = h; BsL[r][c4 * 4 + 2] = l;
                cvt_split(v.w, h, l); BsH[r][c4 * 4 + 3] = h; BsL[r][c4 * 4 + 3] = l;
            }
        }
        __syncthreads();
#pragma unroll
        for (int ks = 0; ks < 3; ks++) {
            int kb = ks * 8;
            int rl = warp * 16 + (lane >> 2);
            int kc = kb + (lane & 3);
            float ah0 = AsH[rl][kc], ah1 = AsH[rl + 8][kc];
            float ah2 = AsH[rl][kc + 4], ah3 = AsH[rl + 8][kc + 4];
            float al0 = AsL[rl][kc], al1 = AsL[rl + 8][kc];
            float al2 = AsL[rl][kc + 4], al3 = AsL[rl + 8][kc + 4];
#pragma unroll
            for (int nf = 0; nf < 8; nf++) {
                int jr = nf * 8 + (lane >> 2);
                float bh0 = BsH[jr][kc], bh1 = BsH[jr][kc + 4];
                float bl0 = BsL[jr][kc], bl1 = BsL[jr][kc + 4];
                MMA8(acc[nf], al0, al1, al2, al3, bh0, bh1);
                MMA8(acc[nf], ah0, ah1, ah2, ah3, bl0, bl1);
                MMA8(acc[nf], ah0, ah1, ah2, ah3, bh0, bh1);
            }
        }
        __syncthreads();
    }
    // store
    int rl = warp * 16 + (lane >> 2);
    int cq = (lane & 3) * 2;
#pragma unroll
    for (int nf = 0; nf < 8; nf++) {
        int j = j0 + nf * 8 + cq;
        if (j < NJ) {
            float2 v0 = make_float2(acc[nf][0], acc[nf][1]);
            float2 v1 = make_float2(acc[nf][2], acc[nf][3]);
            *reinterpret_cast<float2*>(&L[(size_t)(n0 + rl) * NJ + j]) = v0;
            *reinterpret_cast<float2*>(&L[(size_t)(n0 + rl + 8) * NJ + j]) = v1;
        }
    }
}

// ---------------- K4: out_seg + pred/correct + sinkhorn r1 + class counts ----------------
__global__ __launch_bounds__(256) void post_kernel(const int* __restrict__ gt,
                                                   const float* __restrict__ mg,
                                                   const float* __restrict__ mb,
                                                   const float* __restrict__ L,
                                                   float* __restrict__ out_seg) {
    __shared__ float r1s[NJ];
    __shared__ int ccnt[NCLS];
    int tid = threadIdx.x;
    if (tid < NJ) r1s[tid] = 0.f;
    if (tid < NCLS) ccnt[tid] = 0;
    __syncthreads();
    int n = blockIdx.x * 256 + tid;
    const float* Lr = L + (size_t)n * NJ;
    float mx[NCLS];
    float s = 0.f, s2 = 0.f;
#pragma unroll
    for (int k = 0; k < NCLS; k++) {
        const float2* p = reinterpret_cast<const float2*>(Lr + k * NPROTO);
        float m = -1e30f;
#pragma unroll
        for (int i = 0; i < 5; i++) { float2 v = p[i]; m = fmaxf(m, fmaxf(v.x, v.y)); }
        mx[k] = m; s += m; s2 += m * m;
    }
    float mu = s * (1.f / NCLS);
    float var = s2 * (1.f / NCLS) - mu * mu;
    float rs = rsqrtf(var + 1e-5f);
    int pred = 0; float best = -1e30f;
    int bbase = (n >> 15) * (NCLS * HW) + (n & (HW - 1));
#pragma unroll
    for (int k = 0; k < NCLS; k++) {
        float o = (mx[k] - mu) * rs * __ldg(&mg[k]) + __ldg(&mb[k]);
        out_seg[bbase + k * HW] = o;
        if (o > best) { best = o; pred = k; }
    }
    int kg = gt[n];
    g_corr[n] = (unsigned char)(pred == kg);
    atomicAdd(&ccnt[kg], 1);
    const float* lk = Lr + kg * NPROTO;
#pragma unroll
    for (int m = 0; m < NPROTO; m++)
        atomicAdd(&r1s[kg * NPROTO + m], expf(20.f * lk[m]));
    __syncthreads();
    if (tid < NJ) atomicAdd(&g_r[tid], r1s[tid]);
    if (tid < NCLS) atomicAdd(&g_clscnt[tid], ccnt[tid]);
}

// ---------------- K5a: sinkhorn row step ----------------
__global__ void rowstep_kernel(int it) {
    int t = blockIdx.x * blockDim.x + threadIdx.x;
    if (t < NJ) g_a[t] = 1.f / ((float)NPROTO * fmaxf(g_r[it * NJ + t], 1e-12f));
}

// ---------------- K5b: sinkhorn column step + next row sums ----------------
__global__ __launch_bounds__(256) void colstep_kernel(const int* __restrict__ gt,
                                                      const float* __restrict__ L,
                                                      int it_out) {
    __shared__ float rs[NJ], sa[NJ], sbk[NCLS];
    int tid = threadIdx.x;
    if (tid < NJ) { rs[tid] = 0.f; sa[tid] = g_a[tid]; }
    if (tid < NCLS) sbk[tid] = fmaxf((float)g_clscnt[tid], 1.f);
    __syncthreads();
    int n = blockIdx.x * 256 + tid;
    int k = gt[n];
    const float* lk = L + (size_t)n * NJ + k * NPROTO;
    float e[NPROTO];
    float cs = 0.f;
#pragma unroll
    for (int m = 0; m < NPROTO; m++) {
        e[m] = expf(20.f * lk[m]);
        cs += e[m] * sa[k * NPROTO + m];
    }
    float bn = 1.f / (fmaxf(cs, 1e-12f) * sbk[k]);
#pragma unroll
    for (int m = 0; m < NPROTO; m++)
        atomicAdd(&rs[k * NPROTO + m], e[m] * bn);
    __syncthreads();
    if (tid < NJ) atomicAdd(&g_r[it_out * NJ + tid], rs[tid]);
}

// ---------------- K6: final assignment, proto_target, f accumulation ----------------
__global__ __launch_bounds__(256) void assign_kernel(const int* __restrict__ gt,
                                                     const float* __restrict__ L,
                                                     float* __restrict__ target) {
    __shared__ float sa[NJ];
    int tid = threadIdx.x;
    if (tid < NJ) sa[tid] = g_a[tid];
    __syncthreads();
    int n = blockIdx.x * 256 + tid;
    int k = gt[n];
    const float* lk = L + (size_t)n * NJ + k * NPROTO;
    float best = -1.f; int idx = 0;
#pragma unroll
    for (int m = 0; m < NPROTO; m++) {
        float v = expf(20.f * lk[m]) * sa[k * NPROTO + m];
        if (v > best) { best = v; idx = m; }
    }
    target[n] = (float)(idx + NPROTO * k);
    if (g_corr[n]) {
        int j = k * NPROTO + idx;
        atomicAdd(&g_cntkm[j], 1.f);
        const float* cr = g_c + (size_t)n * DIM;
        float* fr = g_f + j * DIM;
#pragma unroll 4
        for (int d = 0; d < DIM; d++) atomicAdd(&fr[d], cr[d]);
    }
}

// ---------------- K7: EMA prototype update + final l2 normalize ----------------
__global__ void protos_new_kernel(float* __restrict__ out) {
    __shared__ float red[256];
    __shared__ float sv[DIM];
    int j = blockIdx.x, tid = threadIdx.x;
    const float* f = g_f + j * DIM;
    float ss = 0.f;
    for (int d = tid; d < DIM; d += 256) { float v = f[d]; ss += v * v; }
    red[tid] = ss; __syncthreads();
    for (int s = 128; s > 0; s >>= 1) { if (tid < s) red[tid] += red[tid + s]; __syncthreads(); }
    float invf = 1.f / fmaxf(sqrtf(red[0]), 1e-12f);
    bool upd = g_cntkm[j] > 0.f;
    __syncthreads();
    float ss2 = 0.f;
    for (int d = tid; d < DIM; d += 256) {
        float p = g_protos[j * DIM + d];
        float v = upd ? (0.999f * p + 0.001f * f[d] * invf) : p;
        sv[d] = v; ss2 += v * v;
    }
    red[tid] = ss2; __syncthreads();
    for (int s = 128; s > 0; s >>= 1) { if (tid < s) red[tid] += red[tid + s]; __syncthreads(); }
    float inv2 = 1.f / fmaxf(sqrtf(red[0]), 1e-12f);
    for (int d = tid; d < DIM; d += 256) out[j * DIM + d] = sv[d] * inv2;
}

// ---------------- launcher ----------------
extern "C" void kernel_launch(void* const* d_in, const int* in_sizes, int n_in,
                              void* d_out, int out_size) {
    const float* c  = (const float*)d_in[0];
    const int*   gt = (const int*)d_in[1];
    const float* pr = (const float*)d_in[2];
    const float* fg = (const float*)d_in[3];
    const float* fb = (const float*)d_in[4];
    const float* mg = (const float*)d_in[5];
    const float* mb = (const float*)d_in[6];
    float* out = (float*)d_out;
    float* out_seg = out;                       // 2,490,368
    float* logits  = out + 2490368;             // 24,903,680
    float* target  = out + 27394048;            // 131,072
    float* pnew    = out + 27525120;            // 136,800

    zero_kernel<<<(NJ * DIM + 255) / 256, 256>>>();
    proto_norm_kernel<<<NJ, 256>>>(pr);
    feat_kernel<<<NPIX / 256, 256>>>(c, fg, fb);
    gemm_kernel<<<dim3(3, NPIX / 128), 256>>>(logits);
    post_kernel<<<NPIX / 256, 256>>>(gt, mg, mb, logits, out_seg);
    rowstep_kernel<<<1, 192>>>(0);
    colstep_kernel<<<NPIX / 256, 256>>>(gt, logits, 1);
    rowstep_kernel<<<1, 192>>>(1);
    colstep_kernel<<<NPIX / 256, 256>>>(gt, logits, 2);
    rowstep_kernel<<<1, 192>>>(2);
    assign_kernel<<<NPIX / 256, 256>>>(gt, logits, target);
    protos_new_kernel<<<NJ, 256>>>(pnew);
}